// round 1
// baseline (speedup 1.0000x reference)
#include <cuda_runtime.h>
#include <stdint.h>

// MultiIndexSelect: out[to_s[j]] = mat_s[from_s[j]] for s in {0,1,2}, j in [0,L)
// D = 64 floats per row = 16 float4 = 256 bytes.
// Layout: 16 threads per row, each moves one float4. blockDim=256 -> 16 rows/block.

#define D4 16  // float4s per row

__global__ void __launch_bounds__(256)
multi_index_select_kernel(
    const float4* __restrict__ m0,
    const float4* __restrict__ m1,
    const float4* __restrict__ m2,
    const int*    __restrict__ f0,
    const int*    __restrict__ f1,
    const int*    __restrict__ f2,
    const int*    __restrict__ t0,
    const int*    __restrict__ t1,
    const int*    __restrict__ t2,
    float4*       __restrict__ out,
    int L)
{
    int gtid = blockIdx.x * blockDim.x + threadIdx.x;
    int row  = gtid >> 4;        // global row index in [0, 3L)
    int lane = gtid & 15;        // float4 slot within row

    int total = 3 * L;
    if (row >= total) return;

    const float4* src;
    int fr, to;
    if (row < L) {
        fr = __ldg(&f0[row]);
        to = __ldg(&t0[row]);
        src = m0;
    } else if (row < 2 * L) {
        int r = row - L;
        fr = __ldg(&f1[r]);
        to = __ldg(&t1[r]);
        src = m1;
    } else {
        int r = row - 2 * L;
        fr = __ldg(&f2[r]);
        to = __ldg(&t2[r]);
        src = m2;
    }

    float4 v = __ldg(&src[(size_t)fr * D4 + lane]);
    out[(size_t)to * D4 + lane] = v;
}

extern "C" void kernel_launch(void* const* d_in, const int* in_sizes, int n_in,
                              void* d_out, int out_size)
{
    // Input order per reference: mat0, mat1, mat2, from0, from1, from2, to0, to1, to2
    const float4* m0 = (const float4*)d_in[0];
    const float4* m1 = (const float4*)d_in[1];
    const float4* m2 = (const float4*)d_in[2];
    const int* f0 = (const int*)d_in[3];
    const int* f1 = (const int*)d_in[4];
    const int* f2 = (const int*)d_in[5];
    const int* t0 = (const int*)d_in[6];
    const int* t1 = (const int*)d_in[7];
    const int* t2 = (const int*)d_in[8];
    float4* out = (float4*)d_out;

    int L = in_sizes[3];          // 400000
    int total_rows = 3 * L;       // 1.2M
    int threads = 256;
    int rows_per_block = threads / D4;  // 16
    int blocks = (total_rows + rows_per_block - 1) / rows_per_block;

    multi_index_select_kernel<<<blocks, threads>>>(
        m0, m1, m2, f0, f1, f2, t0, t1, t2, out, L);
}

// round 2
// speedup vs baseline: 1.3875x; 1.3875x over previous
#include <cuda_runtime.h>
#include <stdint.h>

// MultiIndexSelect: out[to_s[j]] = mat_s[from_s[j]] for s in {0,1,2}, j in [0,L)
// D = 64 floats per row = 16 float4 = 256 bytes.
// 16 threads per row (one float4 each). 256-thread block covers 64 rows via
// 4 front-batched iterations per thread (MLP=4). Streaming stores keep the
// gather working set resident in L2.

#define D4 16          // float4s per row
#define RPT 4          // rows per thread (batched)
#define ROWS_PER_BLOCK 64

__device__ __forceinline__ void store_streaming(float4* p, float4 v) {
    asm volatile("st.global.cs.v4.f32 [%0], {%1, %2, %3, %4};"
                 :: "l"(p), "f"(v.x), "f"(v.y), "f"(v.z), "f"(v.w) : "memory");
}

__global__ void __launch_bounds__(256)
multi_index_select_kernel(
    const float4* __restrict__ m0,
    const float4* __restrict__ m1,
    const float4* __restrict__ m2,
    const int*    __restrict__ f0,
    const int*    __restrict__ f1,
    const int*    __restrict__ f2,
    const int*    __restrict__ t0,
    const int*    __restrict__ t1,
    const int*    __restrict__ t2,
    float4*       __restrict__ out,
    int L)
{
    const int lane  = threadIdx.x & (D4 - 1);
    const int rsub  = threadIdx.x >> 4;                    // 0..15
    const int rbase = blockIdx.x * ROWS_PER_BLOCK + rsub;  // rows: rbase + 16*i
    const int total = 3 * L;

    int fr[RPT], to[RPT];
    const float4* src[RPT];
    bool valid[RPT];

    // Phase 1: gather all indices (independent loads, batched)
    #pragma unroll
    for (int i = 0; i < RPT; i++) {
        int row = rbase + 16 * i;
        valid[i] = (row < total);
        if (valid[i]) {
            if (row < L) {
                fr[i] = __ldg(&f0[row]);
                to[i] = __ldg(&t0[row]);
                src[i] = m0;
            } else if (row < 2 * L) {
                int r = row - L;
                fr[i] = __ldg(&f1[r]);
                to[i] = __ldg(&t1[r]);
                src[i] = m1;
            } else {
                int r = row - 2 * L;
                fr[i] = __ldg(&f2[r]);
                to[i] = __ldg(&t2[r]);
                src[i] = m2;
            }
        }
    }

    // Phase 2: front-batch the 4 independent payload loads (MLP=4)
    float4 v[RPT];
    #pragma unroll
    for (int i = 0; i < RPT; i++) {
        if (valid[i]) v[i] = __ldg(&src[i][(size_t)fr[i] * D4 + lane]);
    }

    // Phase 3: streaming stores — out is written once, never re-read;
    // keep it from evicting the gather working set in L2.
    #pragma unroll
    for (int i = 0; i < RPT; i++) {
        if (valid[i]) store_streaming(&out[(size_t)to[i] * D4 + lane], v[i]);
    }
}

extern "C" void kernel_launch(void* const* d_in, const int* in_sizes, int n_in,
                              void* d_out, int out_size)
{
    const float4* m0 = (const float4*)d_in[0];
    const float4* m1 = (const float4*)d_in[1];
    const float4* m2 = (const float4*)d_in[2];
    const int* f0 = (const int*)d_in[3];
    const int* f1 = (const int*)d_in[4];
    const int* f2 = (const int*)d_in[5];
    const int* t0 = (const int*)d_in[6];
    const int* t1 = (const int*)d_in[7];
    const int* t2 = (const int*)d_in[8];
    float4* out = (float4*)d_out;

    int L = in_sizes[3];                 // 400000
    int total_rows = 3 * L;              // 1.2M
    int blocks = (total_rows + ROWS_PER_BLOCK - 1) / ROWS_PER_BLOCK;  // 18750

    multi_index_select_kernel<<<blocks, 256>>>(
        m0, m1, m2, f0, f1, f2, t0, t1, t2, out, L);
}

// round 3
// speedup vs baseline: 1.4236x; 1.0260x over previous
#include <cuda_runtime.h>
#include <stdint.h>

// MultiIndexSelect: out[to_s[j]] = mat_s[from_s[j]] for s in {0,1,2}, j in [0,L)
// D = 64 floats per row = 16 float4 = 256 bytes.
//
// Exploits exact divisibility: L=400000, 64 rows per block -> 6250 blocks per
// segment, 18750 total. Every block is full (no bounds checks) and lies
// entirely in ONE segment, so src/from/to pointers are block-uniform (live in
// uniform registers, no per-thread predication). 16 threads per row, 4 rows
// per thread front-batched (MLP=4), streaming stores.

#define D4 16
#define RPT 4
#define ROWS_PER_BLOCK 64
#define BLOCKS_PER_SEG 6250   // L / ROWS_PER_BLOCK

__device__ __forceinline__ void store_streaming(float4* p, float4 v) {
    asm volatile("st.global.cs.v4.f32 [%0], {%1, %2, %3, %4};"
                 :: "l"(p), "f"(v.x), "f"(v.y), "f"(v.z), "f"(v.w) : "memory");
}

__global__ void __launch_bounds__(256)
multi_index_select_kernel(
    const float4* __restrict__ m0,
    const float4* __restrict__ m1,
    const float4* __restrict__ m2,
    const int*    __restrict__ f0,
    const int*    __restrict__ f1,
    const int*    __restrict__ f2,
    const int*    __restrict__ t0,
    const int*    __restrict__ t1,
    const int*    __restrict__ t2,
    float4*       __restrict__ out)
{
    // Block-uniform segment selection (no divergence, uniform-register pointers)
    const int seg = blockIdx.x / BLOCKS_PER_SEG;          // 0, 1, 2
    const int segblk = blockIdx.x - seg * BLOCKS_PER_SEG; // block within segment

    const float4* __restrict__ src = (seg == 0) ? m0 : (seg == 1) ? m1 : m2;
    const int*    __restrict__ fi  = (seg == 0) ? f0 : (seg == 1) ? f1 : f2;
    const int*    __restrict__ ti  = (seg == 0) ? t0 : (seg == 1) ? t1 : t2;

    const int lane = threadIdx.x & (D4 - 1);
    const int rsub = threadIdx.x >> 4;                       // 0..15
    const int rbase = segblk * ROWS_PER_BLOCK + rsub;        // local row in segment

    // Phase 1: batch all index loads (coalesced/broadcast within warps)
    int fr[RPT], to[RPT];
    #pragma unroll
    for (int i = 0; i < RPT; i++) {
        int r = rbase + 16 * i;
        fr[i] = __ldg(&fi[r]);
        to[i] = __ldg(&ti[r]);
    }

    // Phase 2: front-batch 4 independent payload loads (MLP=4)
    float4 v[RPT];
    #pragma unroll
    for (int i = 0; i < RPT; i++) {
        v[i] = __ldg(&src[(size_t)fr[i] * D4 + lane]);
    }

    // Phase 3: streaming stores (output written once, never re-read)
    #pragma unroll
    for (int i = 0; i < RPT; i++) {
        store_streaming(&out[(size_t)to[i] * D4 + lane], v[i]);
    }
}

extern "C" void kernel_launch(void* const* d_in, const int* in_sizes, int n_in,
                              void* d_out, int out_size)
{
    const float4* m0 = (const float4*)d_in[0];
    const float4* m1 = (const float4*)d_in[1];
    const float4* m2 = (const float4*)d_in[2];
    const int* f0 = (const int*)d_in[3];
    const int* f1 = (const int*)d_in[4];
    const int* f2 = (const int*)d_in[5];
    const int* t0 = (const int*)d_in[6];
    const int* t1 = (const int*)d_in[7];
    const int* t2 = (const int*)d_in[8];
    float4* out = (float4*)d_out;

    // 3 * 400000 rows / 64 rows per block = 18750 blocks exactly
    multi_index_select_kernel<<<3 * BLOCKS_PER_SEG, 256>>>(
        m0, m1, m2, f0, f1, f2, t0, t1, t2, out);
}